// round 9
// baseline (speedup 1.0000x reference)
#include <cuda_runtime.h>
#include <cuda_fp16.h>
#include <cstdint>

// Problem constants
#define NIMG   8
#define CDIM   256
#define HWDIM  9216
#define TT     32
#define VV     256
#define TV     8192
#define TILE   128
#define NTILES 64

// k_pos smem: full 128x256 A+B tiles, padded stride 264 halves
#define RS     264
#define SMEM_BYTES_POS (2 * TILE * RS * 2)

// k_negpair smem: two 128x128 K-chunks, padded stride 136 halves
#define CRS    136
#define CHUNK_BYTES (TILE * CRS * 2)          // 34816
#define SMEM_BYTES_NEG (2 * CHUNK_BYTES)      // 69632

#define MAXNEG 2016
#define MAXPOS 2080

#define LOG2E    1.4426950408889634f
#define LOG2E_X2 2.8853900817779268f          // exp(2a-2) = 2^(a*L2 - L2)

// Persistent device scratch
__device__ __half g_feats[(size_t)TV * CDIM];
__device__ float g_neg_sum[TV];
__device__ float g_row_loss[TV];
__device__ float g_logS[TV];
__device__ float g_invS[TV];
__device__ int   g_is64;
__device__ int   g_negcnt;
__device__ int   g_poscnt;
__device__ unsigned short g_negpairs[MAXNEG];
__device__ unsigned short g_pospairs[MAXPOS];

__device__ __forceinline__ float fexp2(float x) {
    float r;
    asm("ex2.approx.f32 %0, %1;" : "=f"(r) : "f"(x));
    return r;
}

// ---------------------------------------------------------------------------
// K_prep: 1 block. dtype detect + zero accumulators + build pair worklists.
// ---------------------------------------------------------------------------
__global__ void k_prep(const unsigned int* __restrict__ w,
                       const int* __restrict__ labels) {
    int tid = threadIdx.x;
    unsigned acc = 0;
    for (int i = tid; i < 4096; i += 256) acc |= w[2 * i + 1];
    #pragma unroll
    for (int o = 16; o; o >>= 1) acc |= __shfl_xor_sync(0xFFFFFFFFu, acc, o);
    __shared__ unsigned sh[8];
    if ((tid & 31) == 0) sh[tid >> 5] = acc;
    __syncthreads();
    if (tid == 0) {
        unsigned t = 0;
        #pragma unroll
        for (int i = 0; i < 8; i++) t |= sh[i];
        g_is64 = (t == 0) ? 1 : 0;
    }
    for (int i = tid; i < TV; i += 256) { g_neg_sum[i] = 0.0f; g_row_loss[i] = 0.0f; }
    if (tid == 0) {
        int nc = 0, pc = 0;
        for (int rt = 0; rt < NTILES; rt++) {
            int Lr = labels[rt >> 1];
            for (int ct = rt; ct < NTILES; ct++) {
                int Lc = labels[ct >> 1];
                unsigned short p = (unsigned short)((rt << 8) | ct);
                if (Lc == Lr) g_pospairs[pc++] = p;
                else          g_negpairs[nc++] = p;    // ct > rt guaranteed
            }
        }
        g_negcnt = nc;
        g_poscnt = pc;
    }
}

// ---------------------------------------------------------------------------
// K1: gather + L2-normalize -> fp16  (R5-measured version: block per sample)
// ---------------------------------------------------------------------------
__global__ void k_gather(const float* __restrict__ features,
                         const int* __restrict__ batch_inds,
                         const void* __restrict__ sample_inds) {
    int i = blockIdx.x;
    int c = threadIdx.x;
    int t = i >> 8;
    int v = i & 255;
    int b = batch_inds[t] & (NIMG - 1);

    long long s;
    if (g_is64) s = ((const long long*)sample_inds)[t * VV + v];
    else        s = (long long)((const int*)sample_inds)[t * VV + v];
    if (s < 0) s = 0;
    if (s >= HWDIM) s = HWDIM - 1;

    float f = features[((size_t)b * CDIM + c) * HWDIM + (size_t)s];

    float ss = f * f;
    #pragma unroll
    for (int o = 16; o; o >>= 1) ss += __shfl_xor_sync(0xFFFFFFFFu, ss, o);
    __shared__ float wsum[8];
    __shared__ float tot;
    if ((c & 31) == 0) wsum[c >> 5] = ss;
    __syncthreads();
    if (c < 8) {
        float w = wsum[c];
        #pragma unroll
        for (int o = 4; o; o >>= 1) w += __shfl_xor_sync(0xFFu, w, o);
        if (c == 0) tot = w;
    }
    __syncthreads();

    float inv = 1.0f / fmaxf(sqrtf(tot), 1e-12f);
    g_feats[(size_t)i * CDIM + c] = __float2half(f * inv);
}

// ---------------------------------------------------------------------------
// ldmatrix / mma helpers
// ---------------------------------------------------------------------------
template<int STRIDE>
__device__ __forceinline__ void ldmA(uint32_t a[4], const __half* base,
                                     int rowBase, int k0, int lane) {
    int row = rowBase + (lane & 15);
    int col = k0 + ((lane >> 4) << 3);
    uint32_t addr = (uint32_t)__cvta_generic_to_shared(base + row * STRIDE + col);
    asm volatile("ldmatrix.sync.aligned.m8n8.x4.shared.b16 {%0,%1,%2,%3}, [%4];"
                 : "=r"(a[0]), "=r"(a[1]), "=r"(a[2]), "=r"(a[3]) : "r"(addr));
}
template<int STRIDE>
__device__ __forceinline__ void ldmB(uint32_t b[2], const __half* base,
                                     int nBase, int k0, int lane) {
    int l   = lane & 15;
    int row = nBase + (l & 7);
    int col = k0 + ((l >> 3) << 3);
    uint32_t addr = (uint32_t)__cvta_generic_to_shared(base + row * STRIDE + col);
    asm volatile("ldmatrix.sync.aligned.m8n8.x2.shared.b16 {%0,%1}, [%2];"
                 : "=r"(b[0]), "=r"(b[1]) : "r"(addr));
}
__device__ __forceinline__ void mma_f16acc(uint32_t c[2], const uint32_t a[4],
                                           const uint32_t b[2]) {
    asm volatile("mma.sync.aligned.m16n8k16.row.col.f16.f16.f16.f16 "
                 "{%0,%1},{%2,%3,%4,%5},{%6,%7},{%0,%1};"
                 : "+r"(c[0]), "+r"(c[1])
                 : "r"(a[0]), "r"(a[1]), "r"(a[2]), "r"(a[3]), "r"(b[0]), "r"(b[1]));
}
__device__ __forceinline__ void mma_f32acc(float c[4], const uint32_t a[4],
                                           const uint32_t b[2]) {
    asm volatile("mma.sync.aligned.m16n8k16.row.col.f32.f16.f16.f32 "
                 "{%0,%1,%2,%3},{%4,%5,%6,%7},{%8,%9},{%0,%1,%2,%3};"
                 : "+f"(c[0]), "+f"(c[1]), "+f"(c[2]), "+f"(c[3])
                 : "r"(a[0]), "r"(a[1]), "r"(a[2]), "r"(a[3]), "r"(b[0]), "r"(b[1]));
}

// ---------------------------------------------------------------------------
// K2 (k_negpair): R5-measured inner structure; compacted worklist grid.
// One different-label pair (rt < ct) per block; K in two 128-chunks; f16 acc.
// ---------------------------------------------------------------------------
extern "C" __global__ void __launch_bounds__(256, 2)
k_negpair() {
    int bx = blockIdx.x;
    if (bx >= g_negcnt) return;
    unsigned p = g_negpairs[bx];
    int rt = (int)(p >> 8), ct = (int)(p & 255);

    extern __shared__ __align__(16) char dynsm[];
    __half* sA = (__half*)dynsm;
    __half* sB = sA + TILE * CRS;

    int tid  = threadIdx.x;
    int lane = tid & 31;
    int wid  = tid >> 5;
    int wr   = wid >> 2;
    int wc   = wid & 3;

    uint32_t acc[4][4][2];
    #pragma unroll
    for (int mt = 0; mt < 4; mt++)
        #pragma unroll
        for (int nt = 0; nt < 4; nt++) { acc[mt][nt][0] = 0u; acc[mt][nt][1] = 0u; }

    #pragma unroll
    for (int kc = 0; kc < 2; kc++) {
        if (kc) __syncthreads();
        {
            const uint4* gm = (const uint4*)g_feats;
            int kq = kc * 16;
            #pragma unroll
            for (int x = 0; x < 8; x++) {
                int idx = tid + x * 256;
                int row = idx >> 4;
                int u   = idx & 15;
                *(uint4*)(sA + row * CRS + u * 8) =
                    gm[(((size_t)(rt * TILE + row)) << 5) + kq + u];
                *(uint4*)(sB + row * CRS + u * 8) =
                    gm[(((size_t)(ct * TILE + row)) << 5) + kq + u];
            }
        }
        __syncthreads();

        #pragma unroll
        for (int ks = 0; ks < 8; ks++) {
            int k0 = ks * 16;
            uint32_t a[4][4], b[4][2];
            #pragma unroll
            for (int mt = 0; mt < 4; mt++)
                ldmA<CRS>(a[mt], sA, wr * 64 + mt * 16, k0, lane);
            #pragma unroll
            for (int nt = 0; nt < 4; nt++)
                ldmB<CRS>(b[nt], sB, wc * 32 + nt * 8, k0, lane);
            #pragma unroll
            for (int mt = 0; mt < 4; mt++)
                #pragma unroll
                for (int nt = 0; nt < 4; nt++)
                    mma_f16acc(acc[mt][nt], a[mt], b[nt]);
        }
    }

    float rAcc[4][2] = {};
    float cAcc[4][2] = {};
    #pragma unroll
    for (int mt = 0; mt < 4; mt++)
        #pragma unroll
        for (int nt = 0; nt < 4; nt++)
            #pragma unroll
            for (int h = 0; h < 2; h++) {
                __half2 pk = *(__half2*)&acc[mt][nt][h];
                float a0 = __low2float(pk), a1 = __high2float(pk);
                float v0 = fexp2(fmaf(a0, LOG2E_X2, -LOG2E_X2));
                float v1 = fexp2(fmaf(a1, LOG2E_X2, -LOG2E_X2));
                rAcc[mt][h] += v0 + v1;
                cAcc[nt][0] += v0;
                cAcc[nt][1] += v1;
            }

    #pragma unroll
    for (int mt = 0; mt < 4; mt++)
        #pragma unroll
        for (int h = 0; h < 2; h++) {
            float v = rAcc[mt][h];
            v += __shfl_xor_sync(0xFFFFFFFFu, v, 1);
            v += __shfl_xor_sync(0xFFFFFFFFu, v, 2);
            if ((lane & 3) == 0) {
                int row = rt * TILE + wr * 64 + mt * 16 + (lane >> 2) + h * 8;
                atomicAdd(&g_neg_sum[row], v);
            }
        }
    #pragma unroll
    for (int nt = 0; nt < 4; nt++)
        #pragma unroll
        for (int cc = 0; cc < 2; cc++) {
            float v = cAcc[nt][cc];
            v += __shfl_xor_sync(0xFFFFFFFFu, v, 4);
            v += __shfl_xor_sync(0xFFFFFFFFu, v, 8);
            v += __shfl_xor_sync(0xFFFFFFFFu, v, 16);
            if (lane < 4) {
                int col = ct * TILE + wc * 32 + nt * 8 + 2 * lane + cc;
                atomicAdd(&g_neg_sum[col], v);
            }
        }
}

// ---------------------------------------------------------------------------
// K_logs: precompute logS / invS
// ---------------------------------------------------------------------------
__global__ void k_logs() {
    int i = blockIdx.x * blockDim.x + threadIdx.x;
    if (i < TV) {
        float S = g_neg_sum[i];
        g_logS[i] = __logf(S);
        g_invS[i] = 1.0f / S;
    }
}

// ---------------------------------------------------------------------------
// K3 (k_pos): one same-label pair (rt <= ct) per block, symmetric scatter.
// ---------------------------------------------------------------------------
__device__ __forceinline__ void load_tile(__half* smx, int rowBase, int tid) {
    const uint4* gm = (const uint4*)g_feats;
    #pragma unroll
    for (int x = 0; x < 16; x++) {
        int idx = tid + x * 256;
        int row = idx >> 5;
        int u   = idx & 31;
        *(uint4*)(smx + row * RS + u * 8) = gm[(((size_t)(rowBase + row)) << 5) + u];
    }
}

extern "C" __global__ void __launch_bounds__(256, 1)
k_pos() {
    int bx = blockIdx.x;
    if (bx >= g_poscnt) return;
    unsigned p = g_pospairs[bx];
    int rt = (int)(p >> 8), ct = (int)(p & 255);
    bool diag = (rt == ct);

    extern __shared__ __align__(16) char dynsm[];
    __half* sA = (__half*)dynsm;
    __half* sB = sA + TILE * RS;

    int tid  = threadIdx.x;
    int lane = tid & 31;
    int wid  = tid >> 5;
    int wr   = wid >> 2;
    int wc   = wid & 3;

    load_tile(sA, rt * TILE, tid);
    load_tile(sB, ct * TILE, tid);
    __syncthreads();

    float acc[4][4][4];
    #pragma unroll
    for (int mt = 0; mt < 4; mt++)
        #pragma unroll
        for (int nt = 0; nt < 4; nt++)
            #pragma unroll
            for (int q = 0; q < 4; q++) acc[mt][nt][q] = 0.0f;

    #pragma unroll
    for (int ks = 0; ks < 16; ks++) {
        int k0 = ks * 16;
        uint32_t a[4][4], b[4][2];
        #pragma unroll
        for (int mt = 0; mt < 4; mt++) ldmA<RS>(a[mt], sA, wr * 64 + mt * 16, k0, lane);
        #pragma unroll
        for (int nt = 0; nt < 4; nt++) ldmB<RS>(b[nt], sB, wc * 32 + nt * 8, k0, lane);
        #pragma unroll
        for (int mt = 0; mt < 4; mt++)
            #pragma unroll
            for (int nt = 0; nt < 4; nt++)
                mma_f32acc(acc[mt][nt], a[mt], b[nt]);
    }

    float cLog[4][2], cInv[4][2];
    float cSum[4][2] = {};
    #pragma unroll
    for (int nt = 0; nt < 4; nt++)
        #pragma unroll
        for (int cc = 0; cc < 2; cc++) {
            int col = ct * TILE + wc * 32 + nt * 8 + ((lane & 3) << 1) + cc;
            cLog[nt][cc] = g_logS[col];
            cInv[nt][cc] = g_invS[col];
        }

    #pragma unroll
    for (int mt = 0; mt < 4; mt++) {
        #pragma unroll
        for (int h = 0; h < 2; h++) {
            int row  = rt * TILE + wr * 64 + mt * 16 + (lane >> 2) + h * 8;
            float ls = g_logS[row];
            float is = g_invS[row];
            float rSum = 0.0f;
            #pragma unroll
            for (int nt = 0; nt < 4; nt++) {
                #pragma unroll
                for (int cc = 0; cc < 2; cc++) {
                    int col = ct * TILE + wc * 32 + nt * 8 + ((lane & 3) << 1) + cc;
                    if (diag && col == row) continue;
                    float a = acc[mt][nt][h * 2 + cc];
                    float l = fmaf(2.0f, a, -2.0f);
                    float e = fexp2(l * LOG2E);
                    float xr = e * is;
                    rSum += l - ls - xr + 0.5f * xr * xr;
                    if (!diag) {
                        float xc = e * cInv[nt][cc];
                        cSum[nt][cc] += l - cLog[nt][cc] - xc + 0.5f * xc * xc;
                    }
                }
            }
            float v = rSum;
            v += __shfl_xor_sync(0xFFFFFFFFu, v, 1);
            v += __shfl_xor_sync(0xFFFFFFFFu, v, 2);
            if ((lane & 3) == 0) atomicAdd(&g_row_loss[row], v);
        }
    }
    if (!diag) {
        #pragma unroll
        for (int nt = 0; nt < 4; nt++)
            #pragma unroll
            for (int cc = 0; cc < 2; cc++) {
                float v = cSum[nt][cc];
                v += __shfl_xor_sync(0xFFFFFFFFu, v, 4);
                v += __shfl_xor_sync(0xFFFFFFFFu, v, 8);
                v += __shfl_xor_sync(0xFFFFFFFFu, v, 16);
                if (lane < 4) {
                    int col = ct * TILE + wc * 32 + nt * 8 + 2 * lane + cc;
                    atomicAdd(&g_row_loss[col], v);
                }
            }
    }
}

// ---------------------------------------------------------------------------
// K4: final reduction
// ---------------------------------------------------------------------------
__global__ void k_final(const int* __restrict__ labels, float* __restrict__ out) {
    __shared__ int   lab[TT];
    __shared__ float invpc[TT];
    __shared__ float ws[8];
    int tid = threadIdx.x;
    if (tid < TT) lab[tid] = labels[tid];
    __syncthreads();
    if (tid < TT) {
        int ns = 0;
        #pragma unroll
        for (int j = 0; j < TT; j++) ns += (lab[j] == lab[tid]);
        invpc[tid] = 1.0f / (float)(ns * VV - 1);
    }
    __syncthreads();

    float s = 0.0f;
    for (int i = tid; i < TV; i += 256) s += g_row_loss[i] * invpc[i >> 8];
    #pragma unroll
    for (int o = 16; o; o >>= 1) s += __shfl_xor_sync(0xFFFFFFFFu, s, o);
    if ((tid & 31) == 0) ws[tid >> 5] = s;
    __syncthreads();
    if (tid == 0) {
        float t = 0.0f;
        #pragma unroll
        for (int w = 0; w < 8; w++) t += ws[w];
        out[0] = -(t / (float)TV);
    }
}

// ---------------------------------------------------------------------------
extern "C" void kernel_launch(void* const* d_in, const int* in_sizes, int n_in,
                              void* d_out, int out_size) {
    const float* features    = (const float*)d_in[0];
    const int*   batch_inds  = (const int*)d_in[1];
    const void*  sample_inds = (const void*)d_in[2];
    const int*   labels      = (const int*)d_in[3];
    float*       out         = (float*)d_out;

    static bool attr_set = false;
    if (!attr_set) {
        cudaFuncSetAttribute(k_negpair, cudaFuncAttributeMaxDynamicSharedMemorySize, SMEM_BYTES_NEG);
        cudaFuncSetAttribute(k_pos,     cudaFuncAttributeMaxDynamicSharedMemorySize, SMEM_BYTES_POS);
        attr_set = true;
    }

    k_prep<<<1, 256>>>((const unsigned int*)sample_inds, labels);
    k_gather<<<TV, 256>>>(features, batch_inds, sample_inds);
    k_negpair<<<MAXNEG, 256, SMEM_BYTES_NEG>>>();
    k_logs<<<TV / 256, 256>>>();
    k_pos<<<MAXPOS, 256, SMEM_BYTES_POS>>>();
    k_final<<<1, 256>>>(labels, out);
}

// round 11
// speedup vs baseline: 1.7383x; 1.7383x over previous
#include <cuda_runtime.h>
#include <cuda_fp16.h>
#include <cstdint>

// Problem constants
#define NIMG   8
#define CDIM   256
#define HWDIM  9216
#define TT     32
#define VV     256
#define TV     8192
#define TILE   128
#define NTILES 64

// k_pos smem: full 128x256 A+B tiles, padded stride 264 halves
#define RS     264
#define SMEM_BYTES_POS (2 * TILE * RS * 2)

// k_negpair smem: 2-stage ring of 128x64 A+B chunks, XOR-swizzled
#define CHUNK_BYTES 16384                      // 128 rows * 64 halves * 2B
#define SMEM_BYTES_NEG (4 * CHUNK_BYTES)       // A0,B0,A1,B1 = 64 KB

#define MAXNEG 2016
#define MAXPOS 2080

#define LOG2E    1.4426950408889634f
#define LOG2E_X2 2.8853900817779268f           // exp(2a-2) = 2^(a*L2 - L2)

// Persistent device scratch
__device__ __half g_feats[(size_t)TV * CDIM];
__device__ float g_neg_sum[TV];
__device__ float g_row_loss[TV];
__device__ int   g_is64;
__device__ int   g_negcnt;
__device__ int   g_poscnt;
__device__ unsigned short g_negpairs[MAXNEG];
__device__ unsigned short g_pospairs[MAXPOS];

__device__ __forceinline__ float fexp2(float x) {
    float r;
    asm("ex2.approx.f32 %0, %1;" : "=f"(r) : "f"(x));
    return r;
}

#define CP_ASYNC16(dst, src) \
    asm volatile("cp.async.cg.shared.global [%0], [%1], 16;" :: "r"(dst), "l"(src))
#define CP_COMMIT()  asm volatile("cp.async.commit_group;" ::: "memory")
#define CP_WAIT(n)   asm volatile("cp.async.wait_group %0;" :: "n"(n) : "memory")

// ---------------------------------------------------------------------------
// K_prep: 1 block. dtype detect + zero accumulators + PARALLEL worklist build.
// ---------------------------------------------------------------------------
__global__ void k_prep(const unsigned int* __restrict__ w,
                       const int* __restrict__ labels) {
    int tid = threadIdx.x;
    // detect int64 layout
    unsigned acc = 0;
    for (int i = tid; i < 4096; i += 256) acc |= w[2 * i + 1];
    #pragma unroll
    for (int o = 16; o; o >>= 1) acc |= __shfl_xor_sync(0xFFFFFFFFu, acc, o);
    __shared__ unsigned sh[8];
    if ((tid & 31) == 0) sh[tid >> 5] = acc;
    // zero accumulators while warps converge
    for (int i = tid; i < TV; i += 256) { g_neg_sum[i] = 0.0f; g_row_loss[i] = 0.0f; }
    if (tid == 0) { g_negcnt = 0; g_poscnt = 0; }
    __syncthreads();
    if (tid == 0) {
        unsigned t = 0;
        #pragma unroll
        for (int i = 0; i < 8; i++) t |= sh[i];
        g_is64 = (t == 0) ? 1 : 0;
    }
    // parallel worklist build over the 4096 (rt,ct) grid, keep rt <= ct
    __shared__ int slab[TT];
    if (tid < TT) slab[tid] = labels[tid];
    __syncthreads();
    for (int idx = tid; idx < NTILES * NTILES; idx += 256) {
        int rt = idx >> 6, ct = idx & 63;
        if (ct < rt) continue;
        unsigned short pr = (unsigned short)((rt << 8) | ct);
        if (slab[rt >> 1] == slab[ct >> 1]) g_pospairs[atomicAdd(&g_poscnt, 1)] = pr;
        else                                g_negpairs[atomicAdd(&g_negcnt, 1)] = pr;
    }
}

// ---------------------------------------------------------------------------
// K1: gather + L2-normalize -> fp16. Warp per sample; 8 strided loads (MLP=8).
// ---------------------------------------------------------------------------
__global__ void __launch_bounds__(256)
k_gather(const float* __restrict__ features,
         const int* __restrict__ batch_inds,
         const void* __restrict__ sample_inds) {
    __shared__ __half stage[8 * 264];
    int tid  = threadIdx.x;
    int lane = tid & 31;
    int wrp  = tid >> 5;
    int i = blockIdx.x * 8 + wrp;
    int t = i >> 8;
    int v = i & 255;
    int b = batch_inds[t] & (NIMG - 1);

    long long s;
    if (g_is64) s = ((const long long*)sample_inds)[t * VV + v];
    else        s = (long long)((const int*)sample_inds)[t * VV + v];
    if (s < 0) s = 0;
    if (s >= HWDIM) s = HWDIM - 1;

    const float* base = features + (size_t)b * CDIM * HWDIM + (size_t)s;
    float f[8];
    #pragma unroll
    for (int k = 0; k < 8; k++)
        f[k] = base[(size_t)(lane + 32 * k) * HWDIM];

    float ss = 0.0f;
    #pragma unroll
    for (int k = 0; k < 8; k++) ss += f[k] * f[k];
    #pragma unroll
    for (int o = 16; o; o >>= 1) ss += __shfl_xor_sync(0xFFFFFFFFu, ss, o);

    float inv = 1.0f / fmaxf(sqrtf(ss), 1e-12f);
    #pragma unroll
    for (int k = 0; k < 8; k++)
        stage[wrp * 264 + lane + 32 * k] = __float2half(f[k] * inv);
    __syncwarp();
    uint4 val = *(uint4*)&stage[wrp * 264 + lane * 8];
    *(uint4*)(g_feats + (size_t)i * CDIM + lane * 8) = val;
}

// ---------------------------------------------------------------------------
// ldmatrix / mma helpers
// ---------------------------------------------------------------------------
template<int STRIDE>
__device__ __forceinline__ void ldmA(uint32_t a[4], const __half* base,
                                     int rowBase, int k0, int lane) {
    int row = rowBase + (lane & 15);
    int col = k0 + ((lane >> 4) << 3);
    uint32_t addr = (uint32_t)__cvta_generic_to_shared(base + row * STRIDE + col);
    asm volatile("ldmatrix.sync.aligned.m8n8.x4.shared.b16 {%0,%1,%2,%3}, [%4];"
                 : "=r"(a[0]), "=r"(a[1]), "=r"(a[2]), "=r"(a[3]) : "r"(addr));
}
template<int STRIDE>
__device__ __forceinline__ void ldmB(uint32_t b[2], const __half* base,
                                     int nBase, int k0, int lane) {
    int l   = lane & 15;
    int row = nBase + (l & 7);
    int col = k0 + ((l >> 3) << 3);
    uint32_t addr = (uint32_t)__cvta_generic_to_shared(base + row * STRIDE + col);
    asm volatile("ldmatrix.sync.aligned.m8n8.x2.shared.b16 {%0,%1}, [%2];"
                 : "=r"(b[0]), "=r"(b[1]) : "r"(addr));
}
// swizzled-chunk variants
__device__ __forceinline__ void ldmA_sw(uint32_t a[4], uint32_t base,
                                        int rowBase, int k0, int lane) {
    int row = rowBase + (lane & 15);
    int u   = (k0 >> 3) + (lane >> 4);
    uint32_t addr = base + (uint32_t)((row * 8 + (u ^ (row & 7))) * 16);
    asm volatile("ldmatrix.sync.aligned.m8n8.x4.shared.b16 {%0,%1,%2,%3}, [%4];"
                 : "=r"(a[0]), "=r"(a[1]), "=r"(a[2]), "=r"(a[3]) : "r"(addr));
}
__device__ __forceinline__ void ldmB_sw(uint32_t b[2], uint32_t base,
                                        int nBase, int k0, int lane) {
    int l   = lane & 15;
    int row = nBase + (l & 7);
    int u   = (k0 >> 3) + (l >> 3);
    uint32_t addr = base + (uint32_t)((row * 8 + (u ^ (row & 7))) * 16);
    asm volatile("ldmatrix.sync.aligned.m8n8.x2.shared.b16 {%0,%1}, [%2];"
                 : "=r"(b[0]), "=r"(b[1]) : "r"(addr));
}

__device__ __forceinline__ void mma_f16acc(uint32_t c[2], const uint32_t a[4],
                                           const uint32_t b[2]) {
    asm volatile("mma.sync.aligned.m16n8k16.row.col.f16.f16.f16.f16 "
                 "{%0,%1},{%2,%3,%4,%5},{%6,%7},{%0,%1};"
                 : "+r"(c[0]), "+r"(c[1])
                 : "r"(a[0]), "r"(a[1]), "r"(a[2]), "r"(a[3]), "r"(b[0]), "r"(b[1]));
}
__device__ __forceinline__ void mma_f32acc(float c[4], const uint32_t a[4],
                                           const uint32_t b[2]) {
    asm volatile("mma.sync.aligned.m16n8k16.row.col.f32.f16.f16.f32 "
                 "{%0,%1,%2,%3},{%4,%5,%6,%7},{%8,%9},{%0,%1,%2,%3};"
                 : "+f"(c[0]), "+f"(c[1]), "+f"(c[2]), "+f"(c[3])
                 : "r"(a[0]), "r"(a[1]), "r"(a[2]), "r"(a[3]), "r"(b[0]), "r"(b[1]));
}

// cp.async one K-chunk stage
__device__ __forceinline__ void stage_load(uint32_t sA, uint32_t sB,
                                           int rtRow, int ctRow, int kc, int tid) {
    #pragma unroll
    for (int x = 0; x < 4; x++) {
        int idx = tid + x * 256;
        int row = idx >> 3;
        int u   = idx & 7;
        uint32_t doff = (uint32_t)((row * 8 + (u ^ (row & 7))) * 16);
        const char* srcA = (const char*)(g_feats
                          + ((size_t)(rtRow + row) << 8) + kc * 64 + u * 8);
        const char* srcB = (const char*)(g_feats
                          + ((size_t)(ctRow + row) << 8) + kc * 64 + u * 8);
        CP_ASYNC16(sA + doff, srcA);
        CP_ASYNC16(sB + doff, srcB);
    }
}

// ---------------------------------------------------------------------------
// K2 (k_negpair): one different-label pair per block; cp.async 2-stage ring.
// ---------------------------------------------------------------------------
extern "C" __global__ void __launch_bounds__(256, 2)
k_negpair() {
    int bx = blockIdx.x;
    if (bx >= g_negcnt) return;
    unsigned p = g_negpairs[bx];
    int rt = (int)(p >> 8), ct = (int)(p & 255);

    extern __shared__ __align__(16) char dynsm[];
    uint32_t smb = (uint32_t)__cvta_generic_to_shared(dynsm);
    uint32_t sA[2] = { smb, smb + 2 * CHUNK_BYTES };
    uint32_t sB[2] = { smb + CHUNK_BYTES, smb + 3 * CHUNK_BYTES };

    int tid  = threadIdx.x;
    int lane = tid & 31;
    int wid  = tid >> 5;
    int wr   = wid >> 2;
    int wc   = wid & 3;
    int rtRow = rt * TILE, ctRow = ct * TILE;

    uint32_t acc[4][4][2];
    #pragma unroll
    for (int mt = 0; mt < 4; mt++)
        #pragma unroll
        for (int nt = 0; nt < 4; nt++) { acc[mt][nt][0] = 0u; acc[mt][nt][1] = 0u; }

    stage_load(sA[0], sB[0], rtRow, ctRow, 0, tid); CP_COMMIT();
    stage_load(sA[1], sB[1], rtRow, ctRow, 1, tid); CP_COMMIT();

    #pragma unroll
    for (int kc = 0; kc < 4; kc++) {
        if (kc == 3) CP_WAIT(0); else CP_WAIT(1);
        __syncthreads();
        int buf = kc & 1;
        #pragma unroll
        for (int ks = 0; ks < 4; ks++) {
            int k0 = ks * 16;
            uint32_t a[4][4], b[4][2];
            #pragma unroll
            for (int mt = 0; mt < 4; mt++)
                ldmA_sw(a[mt], sA[buf], wr * 64 + mt * 16, k0, lane);
            #pragma unroll
            for (int nt = 0; nt < 4; nt++)
                ldmB_sw(b[nt], sB[buf], wc * 32 + nt * 8, k0, lane);
            #pragma unroll
            for (int mt = 0; mt < 4; mt++)
                #pragma unroll
                for (int nt = 0; nt < 4; nt++)
                    mma_f16acc(acc[mt][nt], a[mt], b[nt]);
        }
        if (kc < 2) {
            __syncthreads();
            stage_load(sA[buf], sB[buf], rtRow, ctRow, kc + 2, tid);
            CP_COMMIT();
        }
    }

    float rAcc[4][2] = {};
    float cAcc[4][2] = {};
    #pragma unroll
    for (int mt = 0; mt < 4; mt++)
        #pragma unroll
        for (int nt = 0; nt < 4; nt++)
            #pragma unroll
            for (int h = 0; h < 2; h++) {
                __half2 pk = *(__half2*)&acc[mt][nt][h];
                float a0 = __low2float(pk), a1 = __high2float(pk);
                float v0 = fexp2(fmaf(a0, LOG2E_X2, -LOG2E_X2));
                float v1 = fexp2(fmaf(a1, LOG2E_X2, -LOG2E_X2));
                rAcc[mt][h] += v0 + v1;
                cAcc[nt][0] += v0;
                cAcc[nt][1] += v1;
            }

    #pragma unroll
    for (int mt = 0; mt < 4; mt++)
        #pragma unroll
        for (int h = 0; h < 2; h++) {
            float v = rAcc[mt][h];
            v += __shfl_xor_sync(0xFFFFFFFFu, v, 1);
            v += __shfl_xor_sync(0xFFFFFFFFu, v, 2);
            if ((lane & 3) == 0) {
                int row = rtRow + wr * 64 + mt * 16 + (lane >> 2) + h * 8;
                atomicAdd(&g_neg_sum[row], v);
            }
        }
    #pragma unroll
    for (int nt = 0; nt < 4; nt++)
        #pragma unroll
        for (int cc = 0; cc < 2; cc++) {
            float v = cAcc[nt][cc];
            v += __shfl_xor_sync(0xFFFFFFFFu, v, 4);
            v += __shfl_xor_sync(0xFFFFFFFFu, v, 8);
            v += __shfl_xor_sync(0xFFFFFFFFu, v, 16);
            if (lane < 4) {
                int col = ctRow + wc * 32 + nt * 8 + 2 * lane + cc;
                atomicAdd(&g_neg_sum[col], v);
            }
        }
}

// ---------------------------------------------------------------------------
// K3 (k_pos): one same-label pair (rt <= ct) per block; symmetric scatter;
// logS / invS computed inline (no k_logs kernel).
// ---------------------------------------------------------------------------
__device__ __forceinline__ void load_tile(__half* smx, int rowBase, int tid) {
    const uint4* gm = (const uint4*)g_feats;
    #pragma unroll
    for (int x = 0; x < 16; x++) {
        int idx = tid + x * 256;
        int row = idx >> 5;
        int u   = idx & 31;
        *(uint4*)(smx + row * RS + u * 8) = gm[(((size_t)(rowBase + row)) << 5) + u];
    }
}

extern "C" __global__ void __launch_bounds__(256, 1)
k_pos() {
    int bx = blockIdx.x;
    if (bx >= g_poscnt) return;
    unsigned p = g_pospairs[bx];
    int rt = (int)(p >> 8), ct = (int)(p & 255);
    bool diag = (rt == ct);

    extern __shared__ __align__(16) char dynsm[];
    __half* sA = (__half*)dynsm;
    __half* sB = sA + TILE * RS;

    int tid  = threadIdx.x;
    int lane = tid & 31;
    int wid  = tid >> 5;
    int wr   = wid >> 2;
    int wc   = wid & 3;

    load_tile(sA, rt * TILE, tid);
    load_tile(sB, ct * TILE, tid);
    __syncthreads();

    float acc[4][4][4];
    #pragma unroll
    for (int mt = 0; mt < 4; mt++)
        #pragma unroll
        for (int nt = 0; nt < 4; nt++)
            #pragma unroll
            for (int q = 0; q < 4; q++) acc[mt][nt][q] = 0.0f;

    #pragma unroll
    for (int ks = 0; ks < 16; ks++) {
        int k0 = ks * 16;
        uint32_t a[4][4], b[4][2];
        #pragma unroll
        for (int mt = 0; mt < 4; mt++) ldmA<RS>(a[mt], sA, wr * 64 + mt * 16, k0, lane);
        #pragma unroll
        for (int nt = 0; nt < 4; nt++) ldmB<RS>(b[nt], sB, wc * 32 + nt * 8, k0, lane);
        #pragma unroll
        for (int mt = 0; mt < 4; mt++)
            #pragma unroll
            for (int nt = 0; nt < 4; nt++)
                mma_f32acc(acc[mt][nt], a[mt], b[nt]);
    }

    float cLog[4][2], cInv[4][2];
    float cSum[4][2] = {};
    #pragma unroll
    for (int nt = 0; nt < 4; nt++)
        #pragma unroll
        for (int cc = 0; cc < 2; cc++) {
            int col = ct * TILE + wc * 32 + nt * 8 + ((lane & 3) << 1) + cc;
            float S = g_neg_sum[col];
            cLog[nt][cc] = __logf(S);
            cInv[nt][cc] = 1.0f / S;
        }

    #pragma unroll
    for (int mt = 0; mt < 4; mt++) {
        #pragma unroll
        for (int h = 0; h < 2; h++) {
            int row  = rt * TILE + wr * 64 + mt * 16 + (lane >> 2) + h * 8;
            float Sr = g_neg_sum[row];
            float ls = __logf(Sr);
            float is = 1.0f / Sr;
            float rSum = 0.0f;
            #pragma unroll
            for (int nt = 0; nt < 4; nt++) {
                #pragma unroll
                for (int cc = 0; cc < 2; cc++) {
                    int col = ct * TILE + wc * 32 + nt * 8 + ((lane & 3) << 1) + cc;
                    if (diag && col == row) continue;
                    float a = acc[mt][nt][h * 2 + cc];
                    float l = fmaf(2.0f, a, -2.0f);
                    float e = fexp2(l * LOG2E);
                    float xr = e * is;
                    rSum += l - ls - xr + 0.5f * xr * xr;
                    if (!diag) {
                        float xc = e * cInv[nt][cc];
                        cSum[nt][cc] += l - cLog[nt][cc] - xc + 0.5f * xc * xc;
                    }
                }
            }
            float v = rSum;
            v += __shfl_xor_sync(0xFFFFFFFFu, v, 1);
            v += __shfl_xor_sync(0xFFFFFFFFu, v, 2);
            if ((lane & 3) == 0) atomicAdd(&g_row_loss[row], v);
        }
    }
    if (!diag) {
        #pragma unroll
        for (int nt = 0; nt < 4; nt++)
            #pragma unroll
            for (int cc = 0; cc < 2; cc++) {
                float v = cSum[nt][cc];
                v += __shfl_xor_sync(0xFFFFFFFFu, v, 4);
                v += __shfl_xor_sync(0xFFFFFFFFu, v, 8);
                v += __shfl_xor_sync(0xFFFFFFFFu, v, 16);
                if (lane < 4) {
                    int col = ct * TILE + wc * 32 + nt * 8 + 2 * lane + cc;
                    atomicAdd(&g_row_loss[col], v);
                }
            }
    }
}

// ---------------------------------------------------------------------------
// K4: final reduction
// ---------------------------------------------------------------------------
__global__ void k_final(const int* __restrict__ labels, float* __restrict__ out) {
    __shared__ int   lab[TT];
    __shared__ float invpc[TT];
    __shared__ float ws[8];
    int tid = threadIdx.x;
    if (tid < TT) lab[tid] = labels[tid];
    __syncthreads();
    if (tid < TT) {
        int ns = 0;
        #pragma unroll
        for (int j = 0; j < TT; j++) ns += (lab[j] == lab[tid]);
        invpc[tid] = 1.0f / (float)(ns * VV - 1);
    }
    __syncthreads();

    float s = 0.0f;
    for (int i = tid; i < TV; i += 256) s += g_row_loss[i] * invpc[i >> 8];
    #pragma unroll
    for (int o = 16; o; o >>= 1) s += __shfl_xor_sync(0xFFFFFFFFu, s, o);
    if ((tid & 31) == 0) ws[tid >> 5] = s;
    __syncthreads();
    if (tid == 0) {
        float t = 0.0f;
        #pragma unroll
        for (int w = 0; w < 8; w++) t += ws[w];
        out[0] = -(t / (float)TV);
    }
}

// ---------------------------------------------------------------------------
extern "C" void kernel_launch(void* const* d_in, const int* in_sizes, int n_in,
                              void* d_out, int out_size) {
    const float* features    = (const float*)d_in[0];
    const int*   batch_inds  = (const int*)d_in[1];
    const void*  sample_inds = (const void*)d_in[2];
    const int*   labels      = (const int*)d_in[3];
    float*       out         = (float*)d_out;

    static bool attr_set = false;
    if (!attr_set) {
        cudaFuncSetAttribute(k_negpair, cudaFuncAttributeMaxDynamicSharedMemorySize, SMEM_BYTES_NEG);
        cudaFuncSetAttribute(k_pos,     cudaFuncAttributeMaxDynamicSharedMemorySize, SMEM_BYTES_POS);
        attr_set = true;
    }

    k_prep<<<1, 256>>>((const unsigned int*)sample_inds, labels);
    k_gather<<<TV / 8, 256>>>(features, batch_inds, sample_inds);
    k_negpair<<<MAXNEG, 256, SMEM_BYTES_NEG>>>();
    k_pos<<<MAXPOS, 256, SMEM_BYTES_POS>>>();
    k_final<<<1, 256>>>(labels, out);
}